// round 11
// baseline (speedup 1.0000x reference)
#include <cuda_runtime.h>
#include <cstdint>

#define BB 32
#define LL 128
#define FF 128
#define RR 4096
#define HH (RR >> 1)
#define NPAIRS (BB * (RR / 2))   // 65536 output row pairs
#define CAPP 32                  // entries per pair (mean ~6; P(overflow) ~ 1e-15)

// Scratch (allocation-free: __device__ globals, zero-initialized at load;
// out kernel resets counters after use -> no memset pass needed).
__device__ int  g_pcnt[NPAIRS];
__device__ int4 g_plist[NPAIRS * CAPP];  // (element_id, coeff_row0_bits, coeff_row1_bits, 0)

__device__ __forceinline__ void acc_fma(float4& a, float c, const float4& v) {
    a.x = fmaf(c, v.x, a.x); a.y = fmaf(c, v.y, a.y);
    a.z = fmaf(c, v.z, a.z); a.w = fmaf(c, v.w, a.w);
}

__device__ __forceinline__ void append(int pair, int e, float c0, float c1) {
    int pos = atomicAdd(&g_pcnt[pair], 1);
    if (pos < CAPP)
        g_plist[pair * CAPP + pos] =
            make_int4(e, __float_as_int(c0), __float_as_int(c1), 0);
}

// ---------------------------------------------------------------------------
// Kernel 1: one thread per element. Pair k covers rows (2k, 2k+1).
//   car  (j even)        -> row j/2      : pair j>>2,      slot (j>>1)&1
//   cdr  (j odd, j>=3)   -> row (j-1)/2  : pair (j-1)>>2,  slot ((j-1)>>1)&1
//   cons (j < H)         -> rows 2j,2j+1 : pair j, BOTH slots (one entry!)
__global__ void dti_build_kernel(const float4* __restrict__ arg_w,
                                 const float*  __restrict__ op_dist,
                                 const int* __restrict__ batch_idx,
                                 const int* __restrict__ slot_idx,
                                 const int* __restrict__ role_idx,
                                 int n) {
    int e = blockIdx.x * blockDim.x + threadIdx.x;
    if (e >= n) return;
    int b = __ldg(batch_idx + e);
    int s = __ldg(slot_idx + e);
    int j = __ldg(role_idx + e);
    float4 w = __ldg(arg_w + b * LL + s);
    float d0 = __ldg(op_dist + b * 3 + 0);
    float d1 = __ldg(op_dist + b * 3 + 1);
    float d2 = __ldg(op_dist + b * 3 + 2);
    int pbase = b << 11;                    // R/2 = 2048 pairs per batch

    // car / cdr: one consumer row -> one single-sided entry
    if (!(j & 1)) {
        int row = j >> 1;
        float c = d0 * w.x;
        append(pbase + (row >> 1), e, (row & 1) ? 0.f : c, (row & 1) ? c : 0.f);
    } else if (j >= 3) {
        int row = (j - 1) >> 1;
        float c = d1 * w.y;
        append(pbase + (row >> 1), e, (row & 1) ? 0.f : c, (row & 1) ? c : 0.f);
    }
    // cons: both rows of pair j -> ONE dual-coefficient entry
    if (j < HH) {
        append(pbase + j, e, d2 * w.z, d2 * w.w);
    }
}

// ---------------------------------------------------------------------------
// Kernel 2: ONE WARP PER PAIR. Lane l owns features [4l, 4l+4).
// Each element value is loaded ONCE and applied to both rows.
// cnt and list loads are independent (2 memory levels total).
__global__ __launch_bounds__(256, 6)
void dti_out_kernel(const float4* __restrict__ mem,
                    const float4* __restrict__ root_filler,
                    const float*  __restrict__ op_dist,
                    float4* __restrict__ out) {
    int p = (blockIdx.x * blockDim.x + threadIdx.x) >> 5;   // pair id, < NPAIRS
    int lane = threadIdx.x & 31;

    int cnt = __ldg(&g_pcnt[p]);                            // level-1a
    int4 ent = __ldg(&g_plist[p * CAPP + lane]);            // level-1b (parallel)
    cnt = min(cnt, CAPP);

    // self-clean the counter for the next graph replay
    if (lane == 0) g_pcnt[p] = 0;

    float4 a0 = make_float4(0.f, 0.f, 0.f, 0.f);
    float4 a1 = make_float4(0.f, 0.f, 0.f, 0.f);

    #pragma unroll 1
    for (int i = 0; i < cnt; i += 2) {
        int e0  = __shfl_sync(0xffffffffu, ent.x, i);
        int e1  = __shfl_sync(0xffffffffu, ent.x, (i + 1) & 31);
        int c00 = __shfl_sync(0xffffffffu, ent.y, i);
        int c01 = __shfl_sync(0xffffffffu, ent.z, i);
        int c10 = __shfl_sync(0xffffffffu, ent.y, (i + 1) & 31);
        int c11 = __shfl_sync(0xffffffffu, ent.z, (i + 1) & 31);
        bool h1 = i + 1 < cnt;
        float4 v0, v1;
        v0 = __ldg(mem + (size_t)e0 * (FF / 4) + lane);
        if (h1) v1 = __ldg(mem + (size_t)e1 * (FF / 4) + lane);
        acc_fma(a0, __int_as_float(c00), v0);
        acc_fma(a1, __int_as_float(c01), v0);
        if (h1) {
            acc_fma(a0, __int_as_float(c10), v1);
            acc_fma(a1, __int_as_float(c11), v1);
        }
    }

    // pair 0 of each batch: row 1 += d2 * root_filler[b]
    if ((p & ((RR / 2) - 1)) == 0) {
        int b = p >> 11;
        float d2 = __ldg(op_dist + b * 3 + 2);
        float4 rf = __ldg(root_filler + b * (FF / 4) + lane);
        acc_fma(a1, d2, rf);
    }

    // rows 2k, 2k+1 are contiguous: 1KB span, two streaming stores
    size_t o = (size_t)p * 2 * (FF / 4) + lane;
    __stcs(out + o, a0);
    __stcs(out + o + (FF / 4), a1);
}

// ---------------------------------------------------------------------------
extern "C" void kernel_launch(void* const* d_in, const int* in_sizes, int n_in,
                              void* d_out, int out_size) {
    const float* mem = (const float*)d_in[0];
    const float* aw  = (const float*)d_in[1];
    const float* rf  = (const float*)d_in[2];
    const float* od  = (const float*)d_in[3];
    const int* bi    = (const int*)d_in[4];
    const int* si    = (const int*)d_in[5];
    const int* ri    = (const int*)d_in[6];
    float4* out      = (float4*)d_out;

    int n = in_sizes[4];

    // counters arrive zeroed (static init on first run; self-cleaned by the
    // out kernel on every subsequent run/replay) -> no memset pass.
    dti_build_kernel<<<(n + 511) / 512, 512>>>((const float4*)aw, od, bi, si, ri, n);

    dti_out_kernel<<<NPAIRS * 32 / 256, 256>>>(
        (const float4*)mem, (const float4*)rf, od, out);
}

// round 15
// speedup vs baseline: 1.1995x; 1.1995x over previous
#include <cuda_runtime.h>
#include <cstdint>

#define BB 32
#define LL 128
#define FF 128
#define RR 4096
#define HH (RR >> 1)
#define NROWS (BB * RR)        // 131072 output rows
#define CAPR 32                // per-row list capacity (mean ~6 low rows; P(overflow) ~ 1e-15)

// Scratch (allocation-free: __device__ globals, zero-init at module load; the
// out kernel atomically read-and-clears counters -> no memset pass, no race).
__device__ int  g_rcnt[NROWS];
__device__ int2 g_rlist[NROWS * CAPR];   // (element_id, coeff_bits)

__device__ __forceinline__ void acc_fma2(float2& a, float c, const float2& v) {
    a.x = fmaf(c, v.x, a.x); a.y = fmaf(c, v.y, a.y);
}

__device__ __forceinline__ void append(int row, int e, float c) {
    int pos = atomicAdd(&g_rcnt[row], 1);
    if (pos < CAPR) g_rlist[row * CAPR + pos] = make_int2(e, __float_as_int(c));
}

// ---------------------------------------------------------------------------
// Kernel 1: one thread per element — append (e, coeff) to each consumer row.
//   car : j even          -> row j/2        coeff d0*w0
//   cdr : j odd, j >= 3   -> row (j-1)/2    coeff d1*w1
//   cons: j < H           -> row 2j (d2*w2) and row 2j+1 (d2*w3)
__global__ void dti_build_kernel(const float4* __restrict__ arg_w,
                                 const float*  __restrict__ op_dist,
                                 const int* __restrict__ batch_idx,
                                 const int* __restrict__ slot_idx,
                                 const int* __restrict__ role_idx,
                                 int n) {
    int e = blockIdx.x * blockDim.x + threadIdx.x;
    if (e >= n) return;
    int b = __ldg(batch_idx + e);
    int s = __ldg(slot_idx + e);
    int j = __ldg(role_idx + e);
    float4 w = __ldg(arg_w + b * LL + s);
    float d0 = __ldg(op_dist + b * 3 + 0);
    float d1 = __ldg(op_dist + b * 3 + 1);
    float d2 = __ldg(op_dist + b * 3 + 2);
    int rbase = b << 12;

    if (!(j & 1)) {
        append(rbase + (j >> 1), e, d0 * w.x);          // car
    } else if (j >= 3) {
        append(rbase + ((j - 1) >> 1), e, d1 * w.y);    // cdr
    }
    if (j < HH) {
        append(rbase + 2 * j,     e, d2 * w.z);         // cons even row
        append(rbase + 2 * j + 1, e, d2 * w.w);         // cons odd row
    }
}

// ---------------------------------------------------------------------------
// Kernel 2: TWO WARPS PER OUTPUT ROW (half h owns features [64h, 64h+64);
// lane owns a float2). 262144 warps. Strip-4: 4 independent LDG.64 in flight.
//
// Counter protocol (race-free): the row's unique owner (half 0, lane 0) does
// atomicExch(&cnt, 0) — atomic read-and-clear, no load/store window — and
// publishes the count through shared memory; __syncthreads() orders the smem
// store (barrier drains STS) before all 8 warps read it.
__global__ __launch_bounds__(256, 6)
void dti_out_kernel(const float2* __restrict__ mem,
                    const float2* __restrict__ root_filler,
                    const float*  __restrict__ op_dist,
                    float2* __restrict__ out) {
    __shared__ int scnt[4];                                  // 4 rows per block
    int w = (blockIdx.x * blockDim.x + threadIdx.x) >> 5;    // global warp id
    int lane = threadIdx.x & 31;
    int r = w >> 1;                  // row id, < NROWS
    int half = w & 1;
    int rowInBlock = (threadIdx.x >> 6);                     // 0..3
    int fo = (half << 5) + lane;     // float2 index within row (0..63)

    if (half == 0 && lane == 0)
        scnt[rowInBlock] = atomicExch(&g_rcnt[r], 0);        // read-and-clear
    int2 ent = __ldg(&g_rlist[r * CAPR + lane]);             // parallel, unconditional
    __syncthreads();
    int cnt = min(scnt[rowInBlock], CAPR);

    float2 a = make_float2(0.f, 0.f);

    #pragma unroll 1
    for (int i = 0; i < cnt; i += 4) {
        int e0 = __shfl_sync(0xffffffffu, ent.x, i);
        int e1 = __shfl_sync(0xffffffffu, ent.x, (i + 1) & 31);
        int e2 = __shfl_sync(0xffffffffu, ent.x, (i + 2) & 31);
        int e3 = __shfl_sync(0xffffffffu, ent.x, (i + 3) & 31);
        int c0 = __shfl_sync(0xffffffffu, ent.y, i);
        int c1 = __shfl_sync(0xffffffffu, ent.y, (i + 1) & 31);
        int c2 = __shfl_sync(0xffffffffu, ent.y, (i + 2) & 31);
        int c3 = __shfl_sync(0xffffffffu, ent.y, (i + 3) & 31);
        bool h1 = i + 1 < cnt, h2 = i + 2 < cnt, h3 = i + 3 < cnt;
        float2 v0, v1, v2, v3;
        v0 = __ldg(mem + (size_t)e0 * (FF / 2) + fo);
        if (h1) v1 = __ldg(mem + (size_t)e1 * (FF / 2) + fo);
        if (h2) v2 = __ldg(mem + (size_t)e2 * (FF / 2) + fo);
        if (h3) v3 = __ldg(mem + (size_t)e3 * (FF / 2) + fo);
        acc_fma2(a, __int_as_float(c0), v0);
        if (h1) acc_fma2(a, __int_as_float(c1), v1);
        if (h2) acc_fma2(a, __int_as_float(c2), v2);
        if (h3) acc_fma2(a, __int_as_float(c3), v3);
    }

    if ((r & (RR - 1)) == 1) {      // row 1 of each batch: += d2 * root_filler[b]
        int b = r >> 12;
        float d2 = __ldg(op_dist + b * 3 + 2);
        float2 rf = __ldg(root_filler + b * (FF / 2) + fo);
        acc_fma2(a, d2, rf);
    }

    __stcs(out + (size_t)r * (FF / 2) + fo, a);
}

// ---------------------------------------------------------------------------
extern "C" void kernel_launch(void* const* d_in, const int* in_sizes, int n_in,
                              void* d_out, int out_size) {
    const float* mem = (const float*)d_in[0];
    const float* aw  = (const float*)d_in[1];
    const float* rf  = (const float*)d_in[2];
    const float* od  = (const float*)d_in[3];
    const int* bi    = (const int*)d_in[4];
    const int* si    = (const int*)d_in[5];
    const int* ri    = (const int*)d_in[6];
    float2* out      = (float2*)d_out;

    int n = in_sizes[4];

    // counters arrive zeroed (static init on first run; atomically cleared by
    // the out kernel every run) -> no memset pass.
    dti_build_kernel<<<(n + 511) / 512, 512>>>((const float4*)aw, od, bi, si, ri, n);

    // 2 warps per row: 262144 warps -> 32768 blocks x 256
    dti_out_kernel<<<NROWS * 2 * 32 / 256, 256>>>(
        (const float2*)mem, (const float2*)rf, od, out);
}

// round 16
// speedup vs baseline: 1.9584x; 1.6326x over previous
#include <cuda_runtime.h>
#include <cstdint>

#define BB 32
#define LL 128
#define FF 128
#define RR 4096
#define HH (RR >> 1)
#define NROWS (BB * RR)        // 131072 output rows
#define CAPR 32                // per-row list capacity (low rows Poisson(6); clamped)

// Scratch (allocation-free: __device__ globals, zero-init at module load; the
// out kernel atomically read-and-clears counters -> no memset pass, no race:
// each counter has exactly one reader warp).
__device__ int  g_rcnt[NROWS];
__device__ int2 g_rlist[NROWS * CAPR];   // (element_id, coeff_bits)

__device__ __forceinline__ void acc_fma(float4& a, float c, const float4& v) {
    a.x = fmaf(c, v.x, a.x); a.y = fmaf(c, v.y, a.y);
    a.z = fmaf(c, v.z, a.z); a.w = fmaf(c, v.w, a.w);
}

__device__ __forceinline__ void append(int row, int e, float c) {
    int pos = atomicAdd(&g_rcnt[row], 1);
    if (pos < CAPR) g_rlist[row * CAPR + pos] = make_int2(e, __float_as_int(c));
}

// ---------------------------------------------------------------------------
// Kernel 1: one thread per element — append (e, coeff) to each consumer row.
//   car : j even          -> row j/2        coeff d0*w0
//   cdr : j odd, j >= 3   -> row (j-1)/2    coeff d1*w1
//   cons: j < H           -> row 2j (d2*w2) and row 2j+1 (d2*w3)
__global__ void dti_build_kernel(const float4* __restrict__ arg_w,
                                 const float*  __restrict__ op_dist,
                                 const int* __restrict__ batch_idx,
                                 const int* __restrict__ slot_idx,
                                 const int* __restrict__ role_idx,
                                 int n) {
    int e = blockIdx.x * blockDim.x + threadIdx.x;
    if (e >= n) return;
    int b = __ldg(batch_idx + e);
    int s = __ldg(slot_idx + e);
    int j = __ldg(role_idx + e);
    float4 w = __ldg(arg_w + b * LL + s);
    float d0 = __ldg(op_dist + b * 3 + 0);
    float d1 = __ldg(op_dist + b * 3 + 1);
    float d2 = __ldg(op_dist + b * 3 + 2);
    int rbase = b << 12;

    if (!(j & 1)) {
        append(rbase + (j >> 1), e, d0 * w.x);          // car
    } else if (j >= 3) {
        append(rbase + ((j - 1) >> 1), e, d1 * w.y);    // cdr
    }
    if (j < HH) {
        append(rbase + 2 * j,     e, d2 * w.z);         // cons even row
        append(rbase + 2 * j + 1, e, d2 * w.w);         // cons odd row
    }
}

// ---------------------------------------------------------------------------
// Kernel 2: ONE WARP PER OUTPUT ROW. Lane l owns features [4l, 4l+4).
// Lane 0 atomically reads-and-clears the row counter (single owner -> no
// race, and no memset pass anywhere). List fetched half-width: lanes 0-15
// (128B); cnt > 16 is ~1e-4 probability and handled by a scalar tail.
__global__ __launch_bounds__(256, 6)
void dti_out_kernel(const float4* __restrict__ mem,
                    const float4* __restrict__ root_filler,
                    const float*  __restrict__ op_dist,
                    float4* __restrict__ out) {
    int r = (blockIdx.x * blockDim.x + threadIdx.x) >> 5;   // row id, < NROWS
    int lane = threadIdx.x & 31;

    int cnt0 = 0;
    if (lane == 0) cnt0 = atomicExch(&g_rcnt[r], 0);        // read-and-clear
    int2 ent = make_int2(0, 0);
    if (lane < 16) ent = __ldg(&g_rlist[r * CAPR + lane]);  // 128B coalesced, parallel
    int cnt = min(__shfl_sync(0xffffffffu, cnt0, 0), CAPR);

    float4 a = make_float4(0.f, 0.f, 0.f, 0.f);

    int m1 = min(cnt, 16);
    #pragma unroll 1
    for (int i = 0; i < m1; i += 4) {
        int e0 = __shfl_sync(0xffffffffu, ent.x, i);
        int e1 = __shfl_sync(0xffffffffu, ent.x, (i + 1) & 15);
        int e2 = __shfl_sync(0xffffffffu, ent.x, (i + 2) & 15);
        int e3 = __shfl_sync(0xffffffffu, ent.x, (i + 3) & 15);
        int c0 = __shfl_sync(0xffffffffu, ent.y, i);
        int c1 = __shfl_sync(0xffffffffu, ent.y, (i + 1) & 15);
        int c2 = __shfl_sync(0xffffffffu, ent.y, (i + 2) & 15);
        int c3 = __shfl_sync(0xffffffffu, ent.y, (i + 3) & 15);
        bool h1 = i + 1 < m1, h2 = i + 2 < m1, h3 = i + 3 < m1;
        float4 v0, v1, v2, v3;
        v0 = __ldg(mem + (size_t)e0 * (FF / 4) + lane);
        if (h1) v1 = __ldg(mem + (size_t)e1 * (FF / 4) + lane);
        if (h2) v2 = __ldg(mem + (size_t)e2 * (FF / 4) + lane);
        if (h3) v3 = __ldg(mem + (size_t)e3 * (FF / 4) + lane);
        acc_fma(a, __int_as_float(c0), v0);
        if (h1) acc_fma(a, __int_as_float(c1), v1);
        if (h2) acc_fma(a, __int_as_float(c2), v2);
        if (h3) acc_fma(a, __int_as_float(c3), v3);
    }
    // overflow tail (cnt > 16): probability ~1e-4 per row; scalar uniform loads
    #pragma unroll 1
    for (int i = 16; i < cnt; i++) {
        int2 et = __ldg(&g_rlist[r * CAPR + i]);
        float4 v = __ldg(mem + (size_t)et.x * (FF / 4) + lane);
        acc_fma(a, __int_as_float(et.y), v);
    }

    if ((r & (RR - 1)) == 1) {      // row 1 of each batch: += d2 * root_filler[b]
        int b = r >> 12;
        float d2 = __ldg(op_dist + b * 3 + 2);
        float4 rf = __ldg(root_filler + b * (FF / 4) + lane);
        acc_fma(a, d2, rf);
    }

    __stcs(out + (size_t)r * (FF / 4) + lane, a);
}

// ---------------------------------------------------------------------------
extern "C" void kernel_launch(void* const* d_in, const int* in_sizes, int n_in,
                              void* d_out, int out_size) {
    const float* mem = (const float*)d_in[0];
    const float* aw  = (const float*)d_in[1];
    const float* rf  = (const float*)d_in[2];
    const float* od  = (const float*)d_in[3];
    const int* bi    = (const int*)d_in[4];
    const int* si    = (const int*)d_in[5];
    const int* ri    = (const int*)d_in[6];
    float4* out      = (float4*)d_out;

    int n = in_sizes[4];

    // counters arrive zeroed (static init on first run; atomically cleared by
    // the out kernel every run) -> no memset pass.
    dti_build_kernel<<<(n + 511) / 512, 512>>>((const float4*)aw, od, bi, si, ri, n);

    // one warp per row: 131072 warps -> 16384 blocks x 256
    dti_out_kernel<<<NROWS * 32 / 256, 256>>>(
        (const float4*)mem, (const float4*)rf, od, out);
}